// round 11
// baseline (speedup 1.0000x reference)
#include <cuda_runtime.h>
#include <math.h>

#define N  2048
#define DH 256
#define DK 64
#define FF 32
#define SPLITK 8
#define TP 128            // pairs per logits block tile

typedef unsigned long long u64;

// Scratch (static __device__ globals — allocation-free per harness rules)
__device__ float g_q[N * DK];
__device__ float g_k[N * DK];
__device__ float g_v[N * DH];
__device__ float g_s[(size_t)N * N];                 // scores
__device__ float g_f[(size_t)N * N];                 // logits -> focus
__device__ float g_part[(size_t)SPLITK * N * DH];    // split-K partials

// ---- packed fp32 helpers (f32x2 — 2 FMAs per fma-pipe issue) ----
__device__ __forceinline__ void ffma2(u64& d, u64 a, u64 b) {
  asm("fma.rn.f32x2 %0, %1, %2, %0;" : "+l"(d) : "l"(a), "l"(b));
}
__device__ __forceinline__ u64 pack2(float a, float b) {
  u64 u; asm("mov.b64 %0, {%1, %2};" : "=l"(u) : "f"(a), "f"(b)); return u;
}
__device__ __forceinline__ float2 unpack2(u64 u) {
  float2 f; asm("mov.b64 {%0, %1}, %2;" : "=f"(f.x), "=f"(f.y) : "l"(u)); return f;
}

// ---------------------------------------------------------------------------
// Kernel 1: q = x@Wq+bq, k = x@Wk+bk, v = x@Wv+bv
// ---------------------------------------------------------------------------
__global__ void __launch_bounds__(256) qkv_kernel(
    const float* __restrict__ x,
    const float* __restrict__ Wq, const float* __restrict__ bq,
    const float* __restrict__ Wk, const float* __restrict__ bk,
    const float* __restrict__ Wv, const float* __restrict__ bv) {
  __shared__ float xs[8][DH];
  const int t  = threadIdx.x;
  const int r0 = blockIdx.x * 8;

#pragma unroll
  for (int r = 0; r < 8; r++) xs[r][t] = x[(r0 + r) * DH + t];
  __syncthreads();

  float acc[8];
#pragma unroll
  for (int r = 0; r < 8; r++) acc[r] = 0.f;
  for (int d = 0; d < DH; d++) {
    float w = Wv[d * DH + t];
#pragma unroll
    for (int r = 0; r < 8; r++) acc[r] = fmaf(xs[r][d], w, acc[r]);
  }
  float bvt = bv[t];
#pragma unroll
  for (int r = 0; r < 8; r++) g_v[(r0 + r) * DH + t] = acc[r] + bvt;

  if (t < 128) {
    const float* W = (t < 64) ? Wq : Wk;
    const float* b = (t < 64) ? bq : bk;
    float* outp    = (t < 64) ? g_q : g_k;
    const int c = t & 63;
    float a2[8];
#pragma unroll
    for (int r = 0; r < 8; r++) a2[r] = 0.f;
    for (int d = 0; d < DH; d++) {
      float w = W[d * DK + c];
#pragma unroll
      for (int r = 0; r < 8; r++) a2[r] = fmaf(xs[r][d], w, a2[r]);
    }
    float bb = b[c];
#pragma unroll
    for (int r = 0; r < 8; r++) outp[(r0 + r) * DK + c] = a2[r] + bb;
  }
}

// ---------------------------------------------------------------------------
// Kernel 2: S[i,j] = <k_i, q_j>   (64x64 tile per block, K = 64)
// ---------------------------------------------------------------------------
__global__ void __launch_bounds__(256) scores_kernel() {
  __shared__ float Ks[64][65];
  __shared__ float Qs[64][65];
  const int t  = threadIdx.x;
  const int tx = t & 15, ty = t >> 4;
  const int j0 = blockIdx.x * 64, i0 = blockIdx.y * 64;

#pragma unroll
  for (int p = 0; p < 16; p++) {
    int idx = t + p * 256;
    int c = idx & 63, il = idx >> 6;
    Ks[il][c] = g_k[(i0 + il) * DK + c];
    Qs[il][c] = g_q[(j0 + il) * DK + c];
  }
  __syncthreads();

  float acc[4][4];
#pragma unroll
  for (int r = 0; r < 4; r++)
#pragma unroll
    for (int c = 0; c < 4; c++) acc[r][c] = 0.f;

#pragma unroll 16
  for (int c = 0; c < 64; c++) {
    float rk[4], rq[4];
#pragma unroll
    for (int r = 0; r < 4; r++) rk[r] = Ks[ty * 4 + r][c];
#pragma unroll
    for (int q = 0; q < 4; q++) rq[q] = Qs[tx * 4 + q][c];
#pragma unroll
    for (int r = 0; r < 4; r++)
#pragma unroll
      for (int q = 0; q < 4; q++) acc[r][q] = fmaf(rk[r], rq[q], acc[r][q]);
  }

#pragma unroll
  for (int r = 0; r < 4; r++)
#pragma unroll
    for (int q = 0; q < 4; q++)
      g_s[(size_t)(i0 + ty * 4 + r) * N + j0 + tx * 4 + q] = acc[r][q];
}

// ---------------------------------------------------------------------------
// Kernel 3a: per-pair MLP -> logits, tiled GEMM with packed f32x2 mainloop.
// Block tile: TP=128 pairs x FF=32 outputs. 256 threads.
// W2 is stored lane-duplicated (w,w) in smem so FFMA2 needs no ALU packing.
// ---------------------------------------------------------------------------
__global__ void __launch_bounds__(256) logits_kernel(
    const float* __restrict__ adj, const float* __restrict__ dense,
    const float* __restrict__ W1, const float* __restrict__ b1,
    const float* __restrict__ W2, const float* __restrict__ b2,
    const float* __restrict__ W3, const float* __restrict__ b3) {
  __shared__ __align__(16) float ss[TP], aa[TP], ee[TP];
  __shared__ __align__(16) float h1T[FF][TP + 4];   // [k][p], row 528B (16B mult)
  __shared__ __align__(16) u64   w2d[FF][FF];       // [k][n], duplicated lanes
  __shared__ float w1x[FF], w1y[FF], w1z[FF], b1s[FF], w3s[FF], b2s[FF];
  __shared__ float red[TP][9];

  const int t = threadIdx.x;
  const size_t base = (size_t)blockIdx.x * TP;

  if (t < FF) {
    w1x[t] = W1[t];
    w1y[t] = W1[FF + t];
    w1z[t] = W1[2 * FF + t];
    b1s[t] = b1[t];
    w3s[t] = W3[t];
    b2s[t] = b2[t];
  }
  for (int i = t; i < FF * FF; i += 256) {
    float w = W2[i];
    w2d[i >> 5][i & 31] = pack2(w, w);
  }
  if (t < TP) {
    ss[t] = g_s[base + t];
    aa[t] = adj[base + t];
    ee[t] = dense[base + t];
  }
  const float b3v = b3[0];
  __syncthreads();

  // ---- Phase A: h1T[k][p] = relu(W1 . (s,a,e) + b1) ----
#pragma unroll
  for (int it = 0; it < (TP * FF) / 256; it++) {
    int idx = t + it * 256;
    int p = idx >> 5, k = idx & 31;
    float h = fmaf(ss[p], w1x[k], fmaf(aa[p], w1y[k], fmaf(ee[p], w1z[k], b1s[k])));
    h1T[k][p] = fmaxf(h, 0.f);
  }
  __syncthreads();

  // ---- Phase B: (128x32) = h1 @ W2, packed two pair-rows per f32x2 lane ----
  const int tx = t & 7;        // output cols tx*4 .. tx*4+3
  const int ty = t >> 3;       // pair rows  ty*4 .. ty*4+3

  u64 acc2[2][4];              // [rowpair][col]; lanes = (row 2rp, row 2rp+1)
#pragma unroll
  for (int rp = 0; rp < 2; rp++)
#pragma unroll
    for (int c = 0; c < 4; c++) acc2[rp][c] = 0ULL;

#pragma unroll
  for (int k = 0; k < FF; k++) {
    const ulonglong2 rf  = *reinterpret_cast<const ulonglong2*>(&h1T[k][ty * 4]);
    const ulonglong2 rw0 = *reinterpret_cast<const ulonglong2*>(&w2d[k][tx * 4]);
    const ulonglong2 rw1 = *reinterpret_cast<const ulonglong2*>(&w2d[k][tx * 4 + 2]);
    ffma2(acc2[0][0], rf.x, rw0.x);
    ffma2(acc2[0][1], rf.x, rw0.y);
    ffma2(acc2[0][2], rf.x, rw1.x);
    ffma2(acc2[0][3], rf.x, rw1.y);
    ffma2(acc2[1][0], rf.y, rw0.x);
    ffma2(acc2[1][1], rf.y, rw0.y);
    ffma2(acc2[1][2], rf.y, rw1.x);
    ffma2(acc2[1][3], rf.y, rw1.y);
  }

  // ---- Phase C: +b2, relu, dot w3, 8-way reduce ----
  const float bb0 = b2s[tx * 4 + 0], bb1 = b2s[tx * 4 + 1];
  const float bb2 = b2s[tx * 4 + 2], bb3 = b2s[tx * 4 + 3];
  const float ww0 = w3s[tx * 4 + 0], ww1 = w3s[tx * 4 + 1];
  const float ww2 = w3s[tx * 4 + 2], ww3 = w3s[tx * 4 + 3];
#pragma unroll
  for (int rp = 0; rp < 2; rp++) {
    const float2 a0 = unpack2(acc2[rp][0]);
    const float2 a1 = unpack2(acc2[rp][1]);
    const float2 a2 = unpack2(acc2[rp][2]);
    const float2 a3 = unpack2(acc2[rp][3]);
    float pl = fmaxf(a0.x + bb0, 0.f) * ww0;
    pl = fmaf(fmaxf(a1.x + bb1, 0.f), ww1, pl);
    pl = fmaf(fmaxf(a2.x + bb2, 0.f), ww2, pl);
    pl = fmaf(fmaxf(a3.x + bb3, 0.f), ww3, pl);
    float ph = fmaxf(a0.y + bb0, 0.f) * ww0;
    ph = fmaf(fmaxf(a1.y + bb1, 0.f), ww1, ph);
    ph = fmaf(fmaxf(a2.y + bb2, 0.f), ww2, ph);
    ph = fmaf(fmaxf(a3.y + bb3, 0.f), ww3, ph);
    red[ty * 4 + rp * 2 + 0][tx] = pl;
    red[ty * 4 + rp * 2 + 1][tx] = ph;
  }
  __syncthreads();

  if (t < TP) {
    float l = b3v;
#pragma unroll
    for (int c = 0; c < 8; c++) l += red[t][c];
    g_f[base + t] = l;
  }
}

// ---------------------------------------------------------------------------
// Kernel 3b: row softmax over logits (in place on g_f).  One block per row.
// ---------------------------------------------------------------------------
__global__ void __launch_bounds__(256) softmax_kernel() {
  __shared__ float red[8];
  const int t = threadIdx.x;
  float* row = g_f + (size_t)blockIdx.x * N;

  float v[8];
  float m = -3.402823466e38f;
#pragma unroll
  for (int p = 0; p < 8; p++) {
    v[p] = row[t + p * 256];
    m = fmaxf(m, v[p]);
  }
#pragma unroll
  for (int o = 16; o > 0; o >>= 1) m = fmaxf(m, __shfl_xor_sync(0xffffffffu, m, o));
  if ((t & 31) == 0) red[t >> 5] = m;
  __syncthreads();
  float mm = red[0];
#pragma unroll
  for (int r = 1; r < 8; r++) mm = fmaxf(mm, red[r]);
  __syncthreads();

  float sum = 0.f;
#pragma unroll
  for (int p = 0; p < 8; p++) {
    float e = __expf(v[p] - mm);
    v[p] = e;
    sum += e;
  }
#pragma unroll
  for (int o = 16; o > 0; o >>= 1) sum += __shfl_xor_sync(0xffffffffu, sum, o);
  if ((t & 31) == 0) red[t >> 5] = sum;
  __syncthreads();
  float tot = 0.f;
#pragma unroll
  for (int r = 0; r < 8; r++) tot += red[r];
  const float inv = 1.f / tot;

#pragma unroll
  for (int p = 0; p < 8; p++) row[t + p * 256] = v[p] * inv;
}

// ---------------------------------------------------------------------------
// Kernel 4a: partial out = focus @ v over a K-slice (split-K = 8),
// packed f32x2 along the d (column) axis; focus stored lane-duplicated.
// ---------------------------------------------------------------------------
__global__ void __launch_bounds__(256) out_split_kernel() {
  __shared__ __align__(16) u64   Fsd[32][66];   // [kk][i], dup lanes, row 528B
  __shared__ __align__(16) float Vs[32][68];    // [kk][d], row 272B (16B mult)
  const int t  = threadIdx.x;
  const int tx = t & 15, ty = t >> 4;
  const int d0 = blockIdx.x * 64;
  const int i0 = blockIdx.y * 64;
  const int kbeg = blockIdx.z * (N / SPLITK);
  const int kend = kbeg + (N / SPLITK);

  u64 acc2[4][2];              // [row][colpair]
#pragma unroll
  for (int r = 0; r < 4; r++) {
    acc2[r][0] = 0ULL;
    acc2[r][1] = 0ULL;
  }

  for (int k0 = kbeg; k0 < kend; k0 += 32) {
#pragma unroll
    for (int p = 0; p < 8; p++) {
      int idx = t + p * 256;
      int kk = idx & 31, il = idx >> 5;
      float f = g_f[(size_t)(i0 + il) * N + k0 + kk];
      Fsd[kk][il] = pack2(f, f);
      int dl = idx & 63, k2 = idx >> 6;
      Vs[k2][dl] = g_v[(k0 + k2) * DH + d0 + dl];
    }
    __syncthreads();
#pragma unroll
    for (int kk = 0; kk < 32; kk++) {
      const ulonglong2 rfA = *reinterpret_cast<const ulonglong2*>(&Fsd[kk][ty * 4]);
      const ulonglong2 rfB = *reinterpret_cast<const ulonglong2*>(&Fsd[kk][ty * 4 + 2]);
      const ulonglong2 rv  = *reinterpret_cast<const ulonglong2*>(&Vs[kk][tx * 4]);
      ffma2(acc2[0][0], rfA.x, rv.x);
      ffma2(acc2[0][1], rfA.x, rv.y);
      ffma2(acc2[1][0], rfA.y, rv.x);
      ffma2(acc2[1][1], rfA.y, rv.y);
      ffma2(acc2[2][0], rfB.x, rv.x);
      ffma2(acc2[2][1], rfB.x, rv.y);
      ffma2(acc2[3][0], rfB.y, rv.x);
      ffma2(acc2[3][1], rfB.y, rv.y);
    }
    __syncthreads();
  }

  float* part = g_part + (size_t)blockIdx.z * N * DH;
#pragma unroll
  for (int r = 0; r < 4; r++) {
    const float2 c01 = unpack2(acc2[r][0]);
    const float2 c23 = unpack2(acc2[r][1]);
    float4 o = make_float4(c01.x, c01.y, c23.x, c23.y);
    *reinterpret_cast<float4*>(
        &part[(size_t)(i0 + ty * 4 + r) * DH + d0 + tx * 4]) = o;
  }
}

// ---------------------------------------------------------------------------
// Kernel 4b: reduce split-K partials into the output (float4).
// ---------------------------------------------------------------------------
__global__ void __launch_bounds__(256) out_reduce_kernel(float* __restrict__ outp) {
  const size_t i4 = (size_t)blockIdx.x * 256 + threadIdx.x;   // over N*DH/4
  const float4* p4 = reinterpret_cast<const float4*>(g_part);
  float4 s = p4[i4];
#pragma unroll
  for (int z = 1; z < SPLITK; z++) {
    float4 a = p4[(size_t)z * (N * DH / 4) + i4];
    s.x += a.x; s.y += a.y; s.z += a.z; s.w += a.w;
  }
  reinterpret_cast<float4*>(outp)[i4] = s;
}

// ---------------------------------------------------------------------------
extern "C" void kernel_launch(void* const* d_in, const int* in_sizes, int n_in,
                              void* d_out, int out_size) {
  const float* x     = (const float*)d_in[0];
  const float* adj   = (const float*)d_in[1];
  const float* dense = (const float*)d_in[2];
  const float* Wq    = (const float*)d_in[3];
  const float* bq    = (const float*)d_in[4];
  const float* Wk    = (const float*)d_in[5];
  const float* bk    = (const float*)d_in[6];
  const float* Wv    = (const float*)d_in[7];
  const float* bv    = (const float*)d_in[8];
  const float* W1    = (const float*)d_in[9];
  const float* b1    = (const float*)d_in[10];
  const float* W2    = (const float*)d_in[11];
  const float* b2    = (const float*)d_in[12];
  const float* W3    = (const float*)d_in[13];
  const float* b3    = (const float*)d_in[14];
  float* outp        = (float*)d_out;

  qkv_kernel<<<N / 8, 256>>>(x, Wq, bq, Wk, bk, Wv, bv);
  scores_kernel<<<dim3(N / 64, N / 64), 256>>>();
  logits_kernel<<<(N * N) / TP, 256>>>(adj, dense, W1, b1, W2, b2, W3, b3);
  softmax_kernel<<<N, 256>>>();
  out_split_kernel<<<dim3(DH / 64, N / 64, SPLITK), 256>>>();
  out_reduce_kernel<<<(N * DH) / (256 * 4), 256>>>(outp);
}